// round 14
// baseline (speedup 1.0000x reference)
#include <cuda_runtime.h>

#define BB 32
#define TT 512
#define DD 384
#define D4 96
#define OT 8               // output frames per tile
#define TUP 96             // upsample threads: 1 rep x 96 lanes
#define NOUT 8             // outputs per thread
#define NP 4               // output pairs per thread
#define WMAX 96
#define MAXTILES 512
#define MARGIN 25.0f

// Scratch (__device__ globals: no allocations allowed)
__device__ float g_c[BB * TT];             // gaussian centers (monotone per batch)
__device__ float g_rinv[BB * TT];          // 1/(rng+1e-6)
__device__ ulonglong2 g_csdup[BB * D4][2]; // colsum*1e-6, duplicated {cs,cs} pairs
__device__ int2 g_win[BB * MAXTILES];      // per-tile token windows

#define FMA2(acc, a, b) \
    asm("fma.rn.f32x2 %0, %1, %2, %0;" : "+l"(acc) : "l"(a), "l"(b))
#define DUP(dst, src) \
    asm("mov.b64 %0, {%1, %1};" : "=l"(dst) : "r"(src))
#define STCS4(ptr, val) \
    asm volatile("st.global.cs.v4.f32 [%0], {%1, %2, %3, %4};" \
                 :: "l"(ptr), "f"((val).x), "f"((val).y), "f"((val).z), "f"((val).w) \
                 : "memory")

// ---------------------------------------------------------------------------
// Prep, one block per batch (512 thr): duration scan -> centers/rinv,
// per-tile window binary searches, and the full per-batch feats column sums
// (written pre-combined, pre-scaled by 1e-6, pre-duplicated as {cs,cs} pairs
// so the upsample prologue is just 2 LDG.128).
// ---------------------------------------------------------------------------
__global__ __launch_bounds__(TT) void prep_kernel(const float* __restrict__ feats,
                                                  const float* __restrict__ rng,
                                                  const int* __restrict__ dur,
                                                  int ntiles) {
    int b = blockIdx.x, t = threadIdx.x;
    int lane = t & 31, w = t >> 5;
    __shared__ float4 part[4][D4];
    __shared__ float sc[TT];
    __shared__ float wtot[16];

    // --- full column sums: 4 sub-slices x 128 rows each ---
    if (t < 384) {
        int v = t % D4, sub = t / D4;
        const float4* f4 = (const float4*)feats + ((size_t)b * TT + sub * 128) * D4 + v;
        float4 acc = make_float4(0.f, 0.f, 0.f, 0.f);
#pragma unroll 4
        for (int r = 0; r < 128; r++) {
            float4 f = f4[(size_t)r * D4];
            acc.x += f.x; acc.y += f.y; acc.z += f.z; acc.w += f.w;
        }
        part[sub][v] = acc;
    }

    // --- inclusive scan of durations -> centers (all 512 threads) ---
    float d = (float)dur[b * TT + t];
    float x = d;
#pragma unroll
    for (int off = 1; off < 32; off <<= 1) {
        float y = __shfl_up_sync(0xffffffffu, x, off);
        if (lane >= off) x += y;
    }
    if (lane == 31) wtot[w] = x;
    __syncthreads();

    // combine colsum partials, pack duplicated pairs
    if (t < D4) {
        float4 acc = part[0][t];
#pragma unroll
        for (int s = 1; s < 4; s++) {
            float4 p = part[s][t];
            acc.x += p.x; acc.y += p.y; acc.z += p.z; acc.w += p.w;
        }
        unsigned long long d0, d1, d2, d3;
        DUP(d0, __float_as_uint(acc.x * 1e-6f));
        DUP(d1, __float_as_uint(acc.y * 1e-6f));
        DUP(d2, __float_as_uint(acc.z * 1e-6f));
        DUP(d3, __float_as_uint(acc.w * 1e-6f));
        ulonglong2 p0; p0.x = d0; p0.y = d1;
        ulonglong2 p1; p1.x = d2; p1.y = d3;
        g_csdup[b * D4 + t][0] = p0;
        g_csdup[b * D4 + t][1] = p1;
    }

    if (w == 0 && t < 16) {
        float v = wtot[t];
#pragma unroll
        for (int off = 1; off < 16; off <<= 1) {
            float y = __shfl_up_sync(0x0000ffffu, v, off);
            if (t >= off) v += y;
        }
        wtot[t] = v;
    }
    __syncthreads();
    float c = 0.5f * d + x + (w > 0 ? wtot[w - 1] : 0.0f);
    sc[t] = c;
    g_c[b * TT + t] = c;
    g_rinv[b * TT + t] = 1.0f / (rng[b * TT + t] + 1e-6f);
    __syncthreads();

    // --- per-tile windows: binary search on monotone centers ---
    if (t < ntiles) {
        float lob = (float)(t * OT) - MARGIN;
        float hib = (float)(t * OT + OT - 1) + MARGIN;
        int l = 0, r = TT;
        while (l < r) { int m = (l + r) >> 1; if (sc[m] < lob) l = m + 1; else r = m; }
        int lo0 = l;
        l = 0; r = TT;
        while (l < r) { int m = (l + r) >> 1; if (sc[m] <= hib) l = m + 1; else r = m; }
        int hi0 = l - 1;
        if (hi0 - lo0 + 1 > WMAX) hi0 = lo0 + WMAX - 1;  // safety (step>=1 => never)
        g_win[b * MAXTILES + t] = make_int2(lo0, hi0);
    }
}

// ---------------------------------------------------------------------------
// Main: one block per (batch, OT=8 output frames), 96 threads (1 rep).
// Inner loop identical to the champion (A[col][outpair] f32x2, f duplicated
// via mov.b64 on the parallel alu pipe, single next-j prefetch). Accumulator
// init is 2 LDG.128 from the pre-duplicated colsum table.
// ---------------------------------------------------------------------------
__global__ __launch_bounds__(TUP, 10) void upsample_kernel(const float* __restrict__ feats,
                                                           float* __restrict__ out,
                                                           int outlen) {
    int b = blockIdx.y;
    int tile = blockIdx.x;
    int o0 = tile * OT;
    int tid = threadIdx.x;
    int lane = tid & 31, w = tid >> 5;

    __shared__ __align__(16) float gT[WMAX * OT];  // 3 KB
    __shared__ float ps[3][OT];
    __shared__ float sInv[OT];
    __shared__ float scc[WMAX], sri[WMAX];
    __shared__ int sLo, sHi;

    int2 win = g_win[b * MAXTILES + tile];
    int lo0 = win.x;
    int width = win.y - win.x + 1;  // may be <= 0 (pure-floor region)
    if (width < 0) width = 0;

    if (tid == 0) { sLo = WMAX; sHi = -1; }
    if (tid < width) {
        scc[tid] = g_c[b * TT + lo0 + tid];
        sri[tid] = g_rinv[b * TT + lo0 + tid];
    }

    // Prologue: accumulator init straight from pre-duplicated colsum table.
    int v = tid;
    unsigned long long A[4][NP];
    {
        ulonglong2 c01 = g_csdup[b * D4 + v][0];
        ulonglong2 c23 = g_csdup[b * D4 + v][1];
#pragma unroll
        for (int p = 0; p < NP; p++) {
            A[0][p] = c01.x; A[1][p] = c01.y;
            A[2][p] = c23.x; A[3][p] = c23.y;
        }
    }
    __syncthreads();

    // Phase 1: weights over (j, i) grid
    int jmin = WMAX, jmax = -1;
    for (int idx = tid; idx < width * OT; idx += TUP) {
        int j = idx >> 3, i = idx & 7;
        float c = scc[j], ri = sri[j];
        float z = ((float)(o0 + i) - c) * ri;
        float gg = __expf(-0.5f * z * z) * (ri * 0.3989422804014327f);
        gT[idx] = gg;
        if (gg > 1e-9f) { jmin = min(jmin, j); jmax = max(jmax, j); }
    }
    if (jmax >= 0) { atomicMin(&sLo, jmin); atomicMax(&sHi, jmax); }
    __syncthreads();

    // Row sums: warp w covers j-stripe [32w, 32w+32); lane i < OT accumulates row i.
    if (lane < OT) {
        float s = 0.0f;
        int j0 = w * 32, j1 = min(width, j0 + 32);
        for (int j = j0; j < j1; j++) s += gT[j * OT + lane];
        ps[w][lane] = s;
    }
    __syncthreads();
    if (tid < OT) {
        float s = (float)TT * 1e-6f;  // uniform floor mass
#pragma unroll
        for (int ww = 0; ww < 3; ww++) s += ps[ww][tid];
        sInv[tid] = 1.0f / s;
    }
    __syncthreads();

    // Phase 2: windowed matmul
    const uint4* f4 = (const uint4*)feats + ((size_t)b * TT + lo0) * D4 + v;
    int jlo = sLo, jhi = sHi;
    if (jlo <= jhi) {
        uint4 f = f4[(size_t)jlo * D4];
        for (int j = jlo; j <= jhi; j++) {
            int jn = (j < jhi) ? (j + 1) : jhi;     // clamped, branch-free prefetch
            uint4 fn = f4[(size_t)jn * D4];
            unsigned long long fd0, fd1, fd2, fd3;
            DUP(fd0, f.x); DUP(fd1, f.y); DUP(fd2, f.z); DUP(fd3, f.w);
            const ulonglong2* gp = (const ulonglong2*)&gT[j * OT];
            ulonglong2 gA = gp[0];
            ulonglong2 gB = gp[1];
            FMA2(A[0][0], fd0, gA.x); FMA2(A[1][0], fd1, gA.x);
            FMA2(A[2][0], fd2, gA.x); FMA2(A[3][0], fd3, gA.x);
            FMA2(A[0][1], fd0, gA.y); FMA2(A[1][1], fd1, gA.y);
            FMA2(A[2][1], fd2, gA.y); FMA2(A[3][1], fd3, gA.y);
            FMA2(A[0][2], fd0, gB.x); FMA2(A[1][2], fd1, gB.x);
            FMA2(A[2][2], fd2, gB.x); FMA2(A[3][2], fd3, gB.x);
            FMA2(A[0][3], fd0, gB.y); FMA2(A[1][3], fd1, gB.y);
            FMA2(A[2][3], fd2, gB.y); FMA2(A[3][3], fd3, gB.y);
            f = fn;
        }
    }

    // Epilogue: normalize + streaming store (low halves = even output, high = odd)
#pragma unroll
    for (int p = 0; p < NP; p++) {
        int o = o0 + 2 * p;
        if (o < outlen) {
            float s = sInv[2 * p];
            float4 r;
            r.x = __uint_as_float((unsigned)A[0][p]) * s;
            r.y = __uint_as_float((unsigned)A[1][p]) * s;
            r.z = __uint_as_float((unsigned)A[2][p]) * s;
            r.w = __uint_as_float((unsigned)A[3][p]) * s;
            float* dst = out + (((size_t)b * outlen + o) * D4 + v) * 4;
            STCS4(dst, r);
        }
        if (o + 1 < outlen) {
            float s = sInv[2 * p + 1];
            float4 r;
            r.x = __uint_as_float((unsigned)(A[0][p] >> 32)) * s;
            r.y = __uint_as_float((unsigned)(A[1][p] >> 32)) * s;
            r.z = __uint_as_float((unsigned)(A[2][p] >> 32)) * s;
            r.w = __uint_as_float((unsigned)(A[3][p] >> 32)) * s;
            float* dst = out + (((size_t)b * outlen + o + 1) * D4 + v) * 4;
            STCS4(dst, r);
        }
    }
}

extern "C" void kernel_launch(void* const* d_in, const int* in_sizes, int n_in,
                              void* d_out, int out_size) {
    const float* feats = (const float*)d_in[0];
    const float* rng = (const float*)d_in[1];
    const int* dur = (const int*)d_in[2];
    float* out = (float*)d_out;

    int outlen = out_size / (BB * DD);
    int ntiles = (outlen + OT - 1) / OT;

    prep_kernel<<<BB, TT>>>(feats, rng, dur, ntiles);
    upsample_kernel<<<dim3(ntiles, BB), TUP>>>(feats, out, outlen);
}

// round 15
// speedup vs baseline: 1.6106x; 1.6106x over previous
#include <cuda_runtime.h>

#define BB 32
#define TT 512
#define DD 384
#define D4 96
#define OT 8               // output frames per tile
#define TUP 96             // upsample threads: 1 rep x 96 lanes
#define NOUT 8             // outputs per thread
#define NP 4               // output pairs per thread
#define WMAX 96
#define MAXTILES 512
#define NCHUNK 8
#define MARGIN 25.0f

// Scratch (__device__ globals: no allocations allowed)
__device__ float g_c[BB * TT];                 // gaussian centers (monotone per batch)
__device__ float g_rinv[BB * TT];              // 1/(rng+1e-6)
__device__ float4 g_colpart[NCHUNK][BB * D4];  // partial feats column sums
__device__ int2 g_win[BB * MAXTILES];          // per-tile token windows

#define FMA2(acc, a, b) \
    asm("fma.rn.f32x2 %0, %1, %2, %0;" : "+l"(acc) : "l"(a), "l"(b))
#define DUP(dst, src) \
    asm("mov.b64 %0, {%1, %1};" : "=l"(dst) : "r"(src))
#define STCS4(ptr, val) \
    asm volatile("st.global.cs.v4.f32 [%0], {%1, %2, %3, %4};" \
                 :: "l"(ptr), "f"((val).x), "f"((val).y), "f"((val).z), "f"((val).w) \
                 : "memory")

// ---------------------------------------------------------------------------
// Prep, grid (BB, NCHUNK): every block sums its 64-row feats chunk (partials);
// the ky==0 block additionally does the duration scan -> centers/rinv and the
// per-tile window binary searches.
// ---------------------------------------------------------------------------
__global__ __launch_bounds__(TT) void prep_kernel(const float* __restrict__ feats,
                                                  const float* __restrict__ rng,
                                                  const int* __restrict__ dur,
                                                  int ntiles) {
    int b = blockIdx.x, ky = blockIdx.y, t = threadIdx.x;
    int lane = t & 31, w = t >> 5;
    __shared__ float4 part[4][D4];
    __shared__ float sc[TT];
    __shared__ float wtot[16];

    // --- partial column sums: chunk ky = rows [ky*64, ky*64+64), 4 sub-slices ---
    if (t < 384) {
        int v = t % D4, sub = t / D4;
        const float4* f4 = (const float4*)feats + ((size_t)b * TT + ky * 64 + sub * 16) * D4 + v;
        float4 acc = make_float4(0.f, 0.f, 0.f, 0.f);
#pragma unroll
        for (int r = 0; r < 16; r++) {
            float4 f = f4[(size_t)r * D4];
            acc.x += f.x; acc.y += f.y; acc.z += f.z; acc.w += f.w;
        }
        part[sub][v] = acc;
    }
    __syncthreads();
    if (t < D4) {
        float4 acc = part[0][t];
#pragma unroll
        for (int s = 1; s < 4; s++) {
            float4 p = part[s][t];
            acc.x += p.x; acc.y += p.y; acc.z += p.z; acc.w += p.w;
        }
        g_colpart[ky][b * D4 + t] = acc;
    }

    if (ky != 0) return;

    // --- inclusive scan of durations -> centers ---
    float d = (float)dur[b * TT + t];
    float x = d;
#pragma unroll
    for (int off = 1; off < 32; off <<= 1) {
        float y = __shfl_up_sync(0xffffffffu, x, off);
        if (lane >= off) x += y;
    }
    if (lane == 31) wtot[w] = x;
    __syncthreads();
    if (w == 0 && t < 16) {
        float v = wtot[t];
#pragma unroll
        for (int off = 1; off < 16; off <<= 1) {
            float y = __shfl_up_sync(0x0000ffffu, v, off);
            if (t >= off) v += y;
        }
        wtot[t] = v;
    }
    __syncthreads();
    float c = 0.5f * d + x + (w > 0 ? wtot[w - 1] : 0.0f);
    sc[t] = c;
    g_c[b * TT + t] = c;
    g_rinv[b * TT + t] = 1.0f / (rng[b * TT + t] + 1e-6f);
    __syncthreads();

    // --- per-tile windows: binary search on monotone centers ---
    if (t < ntiles) {
        float lob = (float)(t * OT) - MARGIN;
        float hib = (float)(t * OT + OT - 1) + MARGIN;
        int l = 0, r = TT;
        while (l < r) { int m = (l + r) >> 1; if (sc[m] < lob) l = m + 1; else r = m; }
        int lo0 = l;
        l = 0; r = TT;
        while (l < r) { int m = (l + r) >> 1; if (sc[m] <= hib) l = m + 1; else r = m; }
        int hi0 = l - 1;
        if (hi0 - lo0 + 1 > WMAX) hi0 = lo0 + WMAX - 1;  // safety (step>=1 => never)
        g_win[b * MAXTILES + t] = make_int2(lo0, hi0);
    }
}

// ---------------------------------------------------------------------------
// Main: one block per (batch, OT=8 output frames), 96 threads (1 rep).
// Inner loop identical to the R11 champion (A[col][outpair] f32x2, f
// duplicated via mov.b64 on the parallel alu pipe, single next-j prefetch).
// Colsum combine + accumulator init hoisted into the prologue so the 8
// partial LDG.128s are in flight during phase 1 / barriers.
// ---------------------------------------------------------------------------
__global__ __launch_bounds__(TUP, 10) void upsample_kernel(const float* __restrict__ feats,
                                                           float* __restrict__ out,
                                                           int outlen) {
    int b = blockIdx.y;
    int tile = blockIdx.x;
    int o0 = tile * OT;
    int tid = threadIdx.x;
    int lane = tid & 31, w = tid >> 5;

    __shared__ __align__(16) float gT[WMAX * OT];  // 3 KB
    __shared__ float ps[3][OT];
    __shared__ float sInv[OT];
    __shared__ float scc[WMAX], sri[WMAX];
    __shared__ int sLo, sHi;

    int2 win = g_win[b * MAXTILES + tile];
    int lo0 = win.x;
    int width = win.y - win.x + 1;  // may be <= 0 (pure-floor region)
    if (width < 0) width = 0;

    if (tid == 0) { sLo = WMAX; sHi = -1; }
    if (tid < width) {
        scc[tid] = g_c[b * TT + lo0 + tid];
        sri[tid] = g_rinv[b * TT + lo0 + tid];
    }

    // Prologue: combine colsum partials (L2-resident) and init accumulators.
    // These loads depend on nothing -> issue now, hide under phase 1.
    int v = tid;
    unsigned long long A[4][NP];
    {
        float4 cs = make_float4(0.f, 0.f, 0.f, 0.f);
#pragma unroll
        for (int kc = 0; kc < NCHUNK; kc++) {
            float4 p = g_colpart[kc][b * D4 + v];
            cs.x += p.x; cs.y += p.y; cs.z += p.z; cs.w += p.w;
        }
        unsigned long long d0, d1, d2, d3;
        DUP(d0, __float_as_uint(cs.x * 1e-6f));
        DUP(d1, __float_as_uint(cs.y * 1e-6f));
        DUP(d2, __float_as_uint(cs.z * 1e-6f));
        DUP(d3, __float_as_uint(cs.w * 1e-6f));
#pragma unroll
        for (int p = 0; p < NP; p++) { A[0][p] = d0; A[1][p] = d1; A[2][p] = d2; A[3][p] = d3; }
    }
    __syncthreads();

    // Phase 1: weights over (j, i) grid
    int jmin = WMAX, jmax = -1;
    for (int idx = tid; idx < width * OT; idx += TUP) {
        int j = idx >> 3, i = idx & 7;
        float c = scc[j], ri = sri[j];
        float z = ((float)(o0 + i) - c) * ri;
        float gg = __expf(-0.5f * z * z) * (ri * 0.3989422804014327f);
        gT[idx] = gg;
        if (gg > 1e-9f) { jmin = min(jmin, j); jmax = max(jmax, j); }
    }
    if (jmax >= 0) { atomicMin(&sLo, jmin); atomicMax(&sHi, jmax); }
    __syncthreads();

    // Row sums: warp w covers j-stripe [32w, 32w+32); lane i < OT accumulates row i.
    if (lane < OT) {
        float s = 0.0f;
        int j0 = w * 32, j1 = min(width, j0 + 32);
        for (int j = j0; j < j1; j++) s += gT[j * OT + lane];
        ps[w][lane] = s;
    }
    __syncthreads();
    if (tid < OT) {
        float s = (float)TT * 1e-6f;  // uniform floor mass
#pragma unroll
        for (int ww = 0; ww < 3; ww++) s += ps[ww][tid];
        sInv[tid] = 1.0f / s;
    }
    __syncthreads();

    // Phase 2: windowed matmul
    const uint4* f4 = (const uint4*)feats + ((size_t)b * TT + lo0) * D4 + v;
    int jlo = sLo, jhi = sHi;
    if (jlo <= jhi) {
        uint4 f = f4[(size_t)jlo * D4];
        for (int j = jlo; j <= jhi; j++) {
            int jn = (j < jhi) ? (j + 1) : jhi;     // clamped, branch-free prefetch
            uint4 fn = f4[(size_t)jn * D4];
            unsigned long long fd0, fd1, fd2, fd3;
            DUP(fd0, f.x); DUP(fd1, f.y); DUP(fd2, f.z); DUP(fd3, f.w);
            const ulonglong2* gp = (const ulonglong2*)&gT[j * OT];
            ulonglong2 gA = gp[0];
            ulonglong2 gB = gp[1];
            FMA2(A[0][0], fd0, gA.x); FMA2(A[1][0], fd1, gA.x);
            FMA2(A[2][0], fd2, gA.x); FMA2(A[3][0], fd3, gA.x);
            FMA2(A[0][1], fd0, gA.y); FMA2(A[1][1], fd1, gA.y);
            FMA2(A[2][1], fd2, gA.y); FMA2(A[3][1], fd3, gA.y);
            FMA2(A[0][2], fd0, gB.x); FMA2(A[1][2], fd1, gB.x);
            FMA2(A[2][2], fd2, gB.x); FMA2(A[3][2], fd3, gB.x);
            FMA2(A[0][3], fd0, gB.y); FMA2(A[1][3], fd1, gB.y);
            FMA2(A[2][3], fd2, gB.y); FMA2(A[3][3], fd3, gB.y);
            f = fn;
        }
    }

    // Epilogue: normalize + streaming store (low halves = even output, high = odd)
#pragma unroll
    for (int p = 0; p < NP; p++) {
        int o = o0 + 2 * p;
        if (o < outlen) {
            float s = sInv[2 * p];
            float4 r;
            r.x = __uint_as_float((unsigned)A[0][p]) * s;
            r.y = __uint_as_float((unsigned)A[1][p]) * s;
            r.z = __uint_as_float((unsigned)A[2][p]) * s;
            r.w = __uint_as_float((unsigned)A[3][p]) * s;
            float* dst = out + (((size_t)b * outlen + o) * D4 + v) * 4;
            STCS4(dst, r);
        }
        if (o + 1 < outlen) {
            float s = sInv[2 * p + 1];
            float4 r;
            r.x = __uint_as_float((unsigned)(A[0][p] >> 32)) * s;
            r.y = __uint_as_float((unsigned)(A[1][p] >> 32)) * s;
            r.z = __uint_as_float((unsigned)(A[2][p] >> 32)) * s;
            r.w = __uint_as_float((unsigned)(A[3][p] >> 32)) * s;
            float* dst = out + (((size_t)b * outlen + o + 1) * D4 + v) * 4;
            STCS4(dst, r);
        }
    }
}

extern "C" void kernel_launch(void* const* d_in, const int* in_sizes, int n_in,
                              void* d_out, int out_size) {
    const float* feats = (const float*)d_in[0];
    const float* rng = (const float*)d_in[1];
    const int* dur = (const int*)d_in[2];
    float* out = (float*)d_out;

    int outlen = out_size / (BB * DD);
    int ntiles = (outlen + OT - 1) / OT;

    prep_kernel<<<dim3(BB, NCHUNK), TT>>>(feats, rng, dur, ntiles);
    upsample_kernel<<<dim3(ntiles, BB), TUP>>>(feats, out, outlen);
}